// round 9
// baseline (speedup 1.0000x reference)
#include <cuda_runtime.h>
#include <cuda_fp16.h>
#include <cstdint>

#define N_VOX    100000
#define NK       27
#define CENTER_K 13
#define LN_EPS   1e-5f
#define NTHREADS 128
#define GRID_M   ((N_VOX + 127) / 128)   // 782
#define ROWB     144                     // A row stride bytes (72 halves)
#define SLOT_CAP 32

// Shared layout (bytes):
//  accS  [128][68] fp32 : 34816
//  Abig  128*144        : 18432   (sparse phase: warp w bufs at +w*4608, 2x2304)
//  slotV 27*32 int      : 3456
//  slotI 27*32 int      : 3456
//  cnt   27 int (pad)   : 128
#define ACC_OFF   0
#define ABIG_OFF  34816
#define SLOTV_OFF 53248
#define SLOTI_OFF 56704
#define CNT_OFF   60160
#define SMEM_BYTES 60288

__device__ __align__(16) __half    g_f16[N_VOX * 64];
__device__ __align__(16) uint32_t  g_wf[28 * 32 * 64];   // [tap][lane][64] B-fragments

// ---------- helpers ----------
__device__ __forceinline__ uint32_t smem_u32(const void* p) {
    uint32_t a;
    asm("{ .reg .u64 t; cvta.to.shared.u64 t, %1; cvt.u32.u64 %0, t; }" : "=r"(a) : "l"(p));
    return a;
}
__device__ __forceinline__ uint32_t lds32(uint32_t a) {
    uint32_t v;
    asm volatile("ld.shared.b32 %0, [%1];" : "=r"(v) : "r"(a));
    return v;
}
__device__ __forceinline__ void mma16816(float* c, const uint32_t* a,
                                         uint32_t b0, uint32_t b1) {
    asm volatile(
        "mma.sync.aligned.m16n8k16.row.col.f32.f16.f16.f32 "
        "{%0,%1,%2,%3}, {%4,%5,%6,%7}, {%8,%9}, {%0,%1,%2,%3};"
        : "+f"(c[0]), "+f"(c[1]), "+f"(c[2]), "+f"(c[3])
        : "r"(a[0]), "r"(a[1]), "r"(a[2]), "r"(a[3]), "r"(b0), "r"(b1));
}

// ---------- pre-kernels ----------
__global__ void prep_feats(const float* __restrict__ feats) {
    int t = blockIdx.x * blockDim.x + threadIdx.x;       // 8 floats / thread
    if (t >= N_VOX * 8) return;
    const float4* F = (const float4*)feats;
    float4 f0 = F[t * 2], f1 = F[t * 2 + 1];
    __half2 h0 = __floats2half2_rn(f0.x, f0.y);
    __half2 h1 = __floats2half2_rn(f0.z, f0.w);
    __half2 h2 = __floats2half2_rn(f1.x, f1.y);
    __half2 h3 = __floats2half2_rn(f1.z, f1.w);
    uint4 o;
    o.x = *(uint32_t*)&h0; o.y = *(uint32_t*)&h1;
    o.z = *(uint32_t*)&h2; o.w = *(uint32_t*)&h3;
    ((uint4*)g_f16)[t] = o;
}
// Pack W into per-lane mma B fragments: reg = nt*8 + k4*2 + b
// value = half2( W[n][k], W[n][k+1] ), n = nt*8+group, k = k4*16 + qp*2 + b*8
__global__ void prep_wf(const float* __restrict__ Wc, const float* __restrict__ Wl) {
    int e = blockIdx.x * blockDim.x + threadIdx.x;       // 28*2048
    if (e >= 28 * 2048) return;
    int tap = e >> 11, rem = e & 2047;
    int lane = rem >> 6, reg = rem & 63;
    int group = lane >> 2, qp = lane & 3;
    int nt = reg >> 3, k4 = (reg & 7) >> 1, b = reg & 1;
    int n = nt * 8 + group;
    int k = k4 * 16 + qp * 2 + b * 8;
    float w0, w1;
    if (tap < 27) { w0 = Wc[tap * 4096 + k * 64 + n]; w1 = Wc[tap * 4096 + (k + 1) * 64 + n]; }
    else          { w0 = Wl[k * 64 + n];              w1 = Wl[(k + 1) * 64 + n]; }
    __half2 p = __floats2half2_rn(w0, w1);
    g_wf[e] = *(uint32_t*)&p;
}

// ---------- main ----------
__global__ __launch_bounds__(NTHREADS, 3)
void conv_mma_kernel(const int* __restrict__ nb, const float* __restrict__ bc,
                     const float* __restrict__ bl, const float* __restrict__ gamma,
                     const float* __restrict__ beta, float* __restrict__ out)
{
    extern __shared__ __align__(16) char smem[];
    const uint32_t sb = smem_u32(smem);
    float* accS  = (float*)(smem + ACC_OFF);
    int*   slotV = (int*)(smem + SLOTV_OFF);
    int*   slotI = (int*)(smem + SLOTI_OFF);
    int*   cnt   = (int*)(smem + CNT_OFF);

    const int tid   = threadIdx.x;
    const int lane  = tid & 31;
    const int w     = tid >> 5;
    const int group = lane >> 2;
    const int qp    = lane & 3;
    const int gvox  = blockIdx.x * NTHREADS + tid;
    const bool active = gvox < N_VOX;
    const int* nrow = nb + (long)gvox * NK;

    // ---- Phase 0: zero accS + counters ----
    {
        float4 z = make_float4(0.f, 0.f, 0.f, 0.f);
        for (int t = tid; t < 128 * 17; t += NTHREADS) ((float4*)accS)[t] = z;
        if (tid < 27) cnt[tid] = 0;
    }
    __syncthreads();

    // ---- Phase 1: per-tap slot lists ----
    unsigned ovf = 0;
    if (active) {
        #pragma unroll 1
        for (int k = 0; k < NK; k++) {
            if (k == CENTER_K) continue;
            int idx = nrow[k];
            if (idx >= 0) {
                int p = atomicAdd(&cnt[k], 1);
                if (p < SLOT_CAP) { slotV[k * SLOT_CAP + p] = tid; slotI[k * SLOT_CAP + p] = idx; }
                else ovf |= 1u << (k - (k > CENTER_K ? 1 : 0));
            }
        }
    }
    __syncthreads();

    // ---- Phase 2: sparse taps (warp w handles kk % 4 == w) ----
    {
        uint32_t Ab0 = sb + ABIG_OFF + w * 4608;        // two 2304B tile bufs
        #pragma unroll 1
        for (int kk = w; kk < 26; kk += 4) {
            const int k = kk + (kk >= CENTER_K ? 1 : 0);
            const int kcnt = cnt[k] < SLOT_CAP ? cnt[k] : SLOT_CAP;
            if (kcnt == 0) continue;
            // W fragments for this tap (16 x LDG.128)
            uint32_t b[64];
            {
                const uint4* wf = (const uint4*)(g_wf + ((size_t)k * 32 + lane) * 64);
                #pragma unroll
                for (int t = 0; t < 16; t++) {
                    uint4 v = wf[t];
                    b[4 * t] = v.x; b[4 * t + 1] = v.y; b[4 * t + 2] = v.z; b[4 * t + 3] = v.w;
                }
            }
            #pragma unroll 1
            for (int base = 0; base < kcnt; base += 16) {
                uint32_t Ab = Ab0 + ((base >> 4) & 1) * 2304;
                // gather up to 16 rows: lane covers row (lane&15), chunks (lane>>4)+{0,2,4,6}
                {
                    const int r = base + (lane & 15);
                    if (r < kcnt) {
                        const uint4* src = (const uint4*)(g_f16 + (size_t)slotI[k * SLOT_CAP + r] * 64);
                        const int ch = lane >> 4;
                        uint4 u0 = src[ch];
                        uint4 u1 = src[ch + 2];
                        uint4 u2 = src[ch + 4];
                        uint4 u3 = src[ch + 6];
                        char* dst = smem + (Ab - sb) + (lane & 15) * ROWB + ch * 16;
                        *(uint4*)(dst)       = u0;
                        *(uint4*)(dst + 32)  = u1;
                        *(uint4*)(dst + 64)  = u2;
                        *(uint4*)(dst + 96)  = u3;
                    }
                }
                __syncwarp();
                // m16n64k64
                float c8[8][4];
                #pragma unroll
                for (int nt = 0; nt < 8; nt++)
                    #pragma unroll
                    for (int r = 0; r < 4; r++) c8[nt][r] = 0.f;
                #pragma unroll
                for (int k4 = 0; k4 < 4; k4++) {
                    uint32_t a[4];
                    uint32_t abase = Ab + group * ROWB + (k4 * 16 + qp * 2) * 2;
                    a[0] = lds32(abase);
                    a[1] = lds32(abase + 8 * ROWB);
                    a[2] = lds32(abase + 16);
                    a[3] = lds32(abase + 8 * ROWB + 16);
                    #pragma unroll
                    for (int nt = 0; nt < 8; nt++)
                        mma16816(c8[nt], a, b[nt * 8 + k4 * 2], b[nt * 8 + k4 * 2 + 1]);
                }
                // scatter-add into accS
                const int r0 = base + group, r1 = base + group + 8;
                const int v0 = (r0 < kcnt) ? slotV[k * SLOT_CAP + r0] : -1;
                const int v1 = (r1 < kcnt) ? slotV[k * SLOT_CAP + r1] : -1;
                #pragma unroll
                for (int nt = 0; nt < 8; nt++) {
                    const int col = nt * 8 + qp * 2;
                    if (v0 >= 0) {
                        atomicAdd(&accS[v0 * 68 + col],     c8[nt][0]);
                        atomicAdd(&accS[v0 * 68 + col + 1], c8[nt][1]);
                    }
                    if (v1 >= 0) {
                        atomicAdd(&accS[v1 * 68 + col],     c8[nt][2]);
                        atomicAdd(&accS[v1 * 68 + col + 1], c8[nt][3]);
                    }
                }
                __syncwarp();
            }
        }
    }
    // overflow fallback (statistically never taken: needs >32 valid rows for one tap)
    if (ovf) {
        #pragma unroll 1
        for (int kk = 0; kk < 26; kk++) if (ovf & (1u << kk)) {
            const int k = kk + (kk >= CENTER_K ? 1 : 0);
            const __half* f = g_f16 + (size_t)nrow[k] * 64;
            #pragma unroll 1
            for (int nt = 0; nt < 8; nt++) {
                for (int g2 = 0; g2 < 8; g2++) {
                    int n = nt * 8 + g2;
                    float s = 0.f;
                    for (int cc = 0; cc < 64; cc++) {
                        int q2 = (cc >> 1) & 3, k4 = cc >> 4, bsel = (cc >> 3) & 1;
                        int lane2 = g2 * 4 + q2;
                        uint32_t pk = g_wf[((size_t)k * 32 + lane2) * 64 + nt * 8 + k4 * 2 + bsel];
                        __half2 h2 = *(__half2*)&pk;
                        float wv = (cc & 1) ? __high2float(h2) : __low2float(h2);
                        s += __half2float(f[cc]) * wv;
                    }
                    atomicAdd(&accS[tid * 68 + n], s);
                }
            }
        }
    }
    __syncthreads();

    // ---- Phase 3: center tap dense + merge ----
    {
        int idx = active ? nrow[CENTER_K] : -1;
        if (idx >= 0) {
            const uint4* src = (const uint4*)(g_f16 + (size_t)idx * 64);
            char* dst = smem + ABIG_OFF + tid * ROWB;
            #pragma unroll
            for (int j = 0; j < 8; j++) *(uint4*)(dst + j * 16) = src[j];
        } else {
            uint4 z = make_uint4(0, 0, 0, 0);
            char* dst = smem + ABIG_OFF + tid * ROWB;
            #pragma unroll
            for (int j = 0; j < 8; j++) *(uint4*)(dst + j * 16) = z;
        }
    }
    uint32_t b[64];
    {
        const uint4* wf = (const uint4*)(g_wf + ((size_t)CENTER_K * 32 + lane) * 64);
        #pragma unroll
        for (int t = 0; t < 16; t++) {
            uint4 v = wf[t];
            b[4 * t] = v.x; b[4 * t + 1] = v.y; b[4 * t + 2] = v.z; b[4 * t + 3] = v.w;
        }
    }
    __syncthreads();

    float c[2][8][4];
    #pragma unroll
    for (int mi = 0; mi < 2; mi++)
        #pragma unroll
        for (int nt = 0; nt < 8; nt++)
            #pragma unroll
            for (int r = 0; r < 4; r++) c[mi][nt][r] = 0.f;
    {
        uint32_t Ab = sb + ABIG_OFF;
        #pragma unroll
        for (int k4 = 0; k4 < 4; k4++) {
            uint32_t a[2][4];
            #pragma unroll
            for (int mi = 0; mi < 2; mi++) {
                uint32_t base = Ab + (w * 32 + mi * 16 + group) * ROWB + (k4 * 16 + qp * 2) * 2;
                a[mi][0] = lds32(base);
                a[mi][1] = lds32(base + 8 * ROWB);
                a[mi][2] = lds32(base + 16);
                a[mi][3] = lds32(base + 8 * ROWB + 16);
            }
            #pragma unroll
            for (int nt = 0; nt < 8; nt++) {
                uint32_t b0 = b[nt * 8 + k4 * 2], b1 = b[nt * 8 + k4 * 2 + 1];
                mma16816(c[0][nt], a[0], b0, b1);
                mma16816(c[1][nt], a[1], b0, b1);
            }
        }
    }
    // merge accS + bc, convert to fp16 X into Abig
    #pragma unroll
    for (int nt = 0; nt < 8; nt++) {
        const int col = nt * 8 + qp * 2;
        const float b0 = bc[col], b1 = bc[col + 1];
        #pragma unroll
        for (int mi = 0; mi < 2; mi++) {
            const int r0 = w * 32 + mi * 16 + group;
            float x0 = c[mi][nt][0] + b0 + accS[r0 * 68 + col];
            float x1 = c[mi][nt][1] + b1 + accS[r0 * 68 + col + 1];
            float x2 = c[mi][nt][2] + b0 + accS[(r0 + 8) * 68 + col];
            float x3 = c[mi][nt][3] + b1 + accS[(r0 + 8) * 68 + col + 1];
            __half2 p0 = __floats2half2_rn(x0, x1);
            __half2 p1 = __floats2half2_rn(x2, x3);
            *(uint32_t*)(smem + ABIG_OFF + r0 * ROWB + col * 2)       = *(uint32_t*)&p0;
            *(uint32_t*)(smem + ABIG_OFF + (r0 + 8) * ROWB + col * 2) = *(uint32_t*)&p1;
        }
    }
    {
        const uint4* wf = (const uint4*)(g_wf + ((size_t)27 * 32 + lane) * 64);
        #pragma unroll
        for (int t = 0; t < 16; t++) {
            uint4 v = wf[t];
            b[4 * t] = v.x; b[4 * t + 1] = v.y; b[4 * t + 2] = v.z; b[4 * t + 3] = v.w;
        }
    }
    __syncthreads();

    // ---- Phase 4: linear GEMM ----
    #pragma unroll
    for (int mi = 0; mi < 2; mi++)
        #pragma unroll
        for (int nt = 0; nt < 8; nt++)
            #pragma unroll
            for (int r = 0; r < 4; r++) c[mi][nt][r] = 0.f;
    {
        uint32_t Ab = sb + ABIG_OFF;
        #pragma unroll
        for (int k4 = 0; k4 < 4; k4++) {
            uint32_t a[2][4];
            #pragma unroll
            for (int mi = 0; mi < 2; mi++) {
                uint32_t base = Ab + (w * 32 + mi * 16 + group) * ROWB + (k4 * 16 + qp * 2) * 2;
                a[mi][0] = lds32(base);
                a[mi][1] = lds32(base + 8 * ROWB);
                a[mi][2] = lds32(base + 16);
                a[mi][3] = lds32(base + 8 * ROWB + 16);
            }
            #pragma unroll
            for (int nt = 0; nt < 8; nt++) {
                uint32_t b0 = b[nt * 8 + k4 * 2], b1 = b[nt * 8 + k4 * 2 + 1];
                mma16816(c[0][nt], a[0], b0, b1);
                mma16816(c[1][nt], a[1], b0, b1);
            }
        }
    }

    // ---- Phase 5: +bl, layernorm, store ----
    float sum[2][2] = {{0.f, 0.f}, {0.f, 0.f}};
    float sq [2][2] = {{0.f, 0.f}, {0.f, 0.f}};
    #pragma unroll
    for (int nt = 0; nt < 8; nt++) {
        const int col = nt * 8 + qp * 2;
        const float b0 = bl[col], b1 = bl[col + 1];
        #pragma unroll
        for (int mi = 0; mi < 2; mi++) {
            float y0 = c[mi][nt][0] + b0, y1 = c[mi][nt][1] + b1;
            float y2 = c[mi][nt][2] + b0, y3 = c[mi][nt][3] + b1;
            c[mi][nt][0] = y0; c[mi][nt][1] = y1;
            c[mi][nt][2] = y2; c[mi][nt][3] = y3;
            sum[mi][0] += y0 + y1;  sq[mi][0] += y0 * y0 + y1 * y1;
            sum[mi][1] += y2 + y3;  sq[mi][1] += y2 * y2 + y3 * y3;
        }
    }
    #pragma unroll
    for (int off = 1; off <= 2; off <<= 1) {
        #pragma unroll
        for (int mi = 0; mi < 2; mi++)
            #pragma unroll
            for (int h = 0; h < 2; h++) {
                sum[mi][h] += __shfl_xor_sync(0xffffffffu, sum[mi][h], off);
                sq [mi][h] += __shfl_xor_sync(0xffffffffu, sq [mi][h], off);
            }
    }
    float mu[2][2], rs[2][2];
    #pragma unroll
    for (int mi = 0; mi < 2; mi++)
        #pragma unroll
        for (int h = 0; h < 2; h++) {
            float m = sum[mi][h] * (1.0f / 64.0f);
            float v = sq[mi][h] * (1.0f / 64.0f) - m * m;
            mu[mi][h] = m;
            rs[mi][h] = rsqrtf(v + LN_EPS);
        }
    const int base_row = blockIdx.x * NTHREADS + w * 32 + group;
    #pragma unroll
    for (int nt = 0; nt < 8; nt++) {
        const int col = nt * 8 + qp * 2;
        const float g0 = gamma[col], g1 = gamma[col + 1];
        const float be0 = beta[col], be1 = beta[col + 1];
        #pragma unroll
        for (int mi = 0; mi < 2; mi++) {
            int r0 = base_row + mi * 16;
            int r1 = r0 + 8;
            if (r0 < N_VOX) {
                float2 o;
                o.x = g0 * (c[mi][nt][0] - mu[mi][0]) * rs[mi][0] + be0;
                o.y = g1 * (c[mi][nt][1] - mu[mi][0]) * rs[mi][0] + be1;
                *(float2*)(out + (size_t)r0 * 64 + col) = o;
            }
            if (r1 < N_VOX) {
                float2 o;
                o.x = g0 * (c[mi][nt][2] - mu[mi][1]) * rs[mi][1] + be0;
                o.y = g1 * (c[mi][nt][3] - mu[mi][1]) * rs[mi][1] + be1;
                *(float2*)(out + (size_t)r1 * 64 + col) = o;
            }
        }
    }
}

// ---------- launch ----------
extern "C" void kernel_launch(void* const* d_in, const int* in_sizes, int n_in,
                              void* d_out, int out_size)
{
    const float* feats = (const float*)d_in[0];
    const int*   nb    = (const int*)d_in[1];
    const float* Wc    = (const float*)d_in[2];
    const float* bc    = (const float*)d_in[3];
    const float* Wl    = (const float*)d_in[4];
    const float* bl    = (const float*)d_in[5];
    const float* gamma = (const float*)d_in[6];
    const float* beta  = (const float*)d_in[7];
    float* out = (float*)d_out;

    static int init = 0;
    if (!init) {
        cudaFuncSetAttribute(conv_mma_kernel,
                             cudaFuncAttributeMaxDynamicSharedMemorySize, SMEM_BYTES);
        init = 1;
    }
    prep_feats<<<(N_VOX * 8 + 255) / 256, 256>>>(feats);
    prep_wf<<<(28 * 2048 + 255) / 256, 256>>>(Wc, Wl);
    conv_mma_kernel<<<GRID_M, NTHREADS, SMEM_BYTES>>>(nb, bc, bl, gamma, beta, out);
}

// round 10
// speedup vs baseline: 1.0406x; 1.0406x over previous
#include <cuda_runtime.h>
#include <cuda_fp16.h>
#include <cstdint>

#define N_VOX    100000
#define NK       27
#define LN_EPS   1e-5f
#define NTHREADS 128
#define GRID_M   ((N_VOX + 127) / 128)   // 782

#define ROWB     144                     // A row stride bytes (72 halves)
#define STAGE_A  18432                   // 128 * 144
#define SMEM_BYTES (2 * STAGE_A)         // 36864

__device__ __align__(16) __half    g_f16[N_VOX * 64];
// B fragments: [tap][nt][lane][8 regs]; reg r = k4*2+bsel,
// value = half2(W[k][n], W[k+1][n]) with n = nt*8+group, k = k4*16+qp*2+bsel*8
__device__ __align__(16) uint32_t  g_wfB[28 * 8 * 32 * 8];

// ---------- helpers ----------
__device__ __forceinline__ uint32_t smem_u32(const void* p) {
    uint32_t a;
    asm("{ .reg .u64 t; cvta.to.shared.u64 t, %1; cvt.u32.u64 %0, t; }" : "=r"(a) : "l"(p));
    return a;
}
__device__ __forceinline__ void cpa16(uint32_t dst, const void* src) {
    asm volatile("cp.async.cg.shared.global [%0], [%1], 16;" :: "r"(dst), "l"(src));
}
#define CP_COMMIT()  asm volatile("cp.async.commit_group;" ::: "memory")
#define CP_WAIT(n)   asm volatile("cp.async.wait_group %0;" :: "n"(n) : "memory")

__device__ __forceinline__ void ldsm4(uint32_t* r, uint32_t addr) {
    asm volatile("ldmatrix.sync.aligned.m8n8.x4.shared.b16 {%0,%1,%2,%3}, [%4];"
                 : "=r"(r[0]), "=r"(r[1]), "=r"(r[2]), "=r"(r[3]) : "r"(addr));
}
__device__ __forceinline__ void mma16816(float* c, const uint32_t* a,
                                         uint32_t b0, uint32_t b1) {
    asm volatile(
        "mma.sync.aligned.m16n8k16.row.col.f32.f16.f16.f32 "
        "{%0,%1,%2,%3}, {%4,%5,%6,%7}, {%8,%9}, {%0,%1,%2,%3};"
        : "+f"(c[0]), "+f"(c[1]), "+f"(c[2]), "+f"(c[3])
        : "r"(a[0]), "r"(a[1]), "r"(a[2]), "r"(a[3]), "r"(b0), "r"(b1));
}

// ---------- pre-kernels ----------
__global__ void prep_feats(const float* __restrict__ feats) {
    int t = blockIdx.x * blockDim.x + threadIdx.x;       // 8 floats / thread
    if (t >= N_VOX * 8) return;
    const float4* F = (const float4*)feats;
    float4 f0 = F[t * 2], f1 = F[t * 2 + 1];
    __half2 h0 = __floats2half2_rn(f0.x, f0.y);
    __half2 h1 = __floats2half2_rn(f0.z, f0.w);
    __half2 h2 = __floats2half2_rn(f1.x, f1.y);
    __half2 h3 = __floats2half2_rn(f1.z, f1.w);
    uint4 o;
    o.x = *(uint32_t*)&h0; o.y = *(uint32_t*)&h1;
    o.z = *(uint32_t*)&h2; o.w = *(uint32_t*)&h3;
    ((uint4*)g_f16)[t] = o;
}
__global__ void prep_wfB(const float* __restrict__ Wc, const float* __restrict__ Wl) {
    int e = blockIdx.x * blockDim.x + threadIdx.x;       // 28*8*32*8 = 57344
    if (e >= 28 * 2048) return;
    int r    = e & 7;
    int lane = (e >> 3) & 31;
    int nt   = (e >> 8) & 7;
    int tap  = e >> 11;
    int group = lane >> 2, qp = lane & 3;
    int k4 = r >> 1, bsel = r & 1;
    int n = nt * 8 + group;
    int k = k4 * 16 + qp * 2 + bsel * 8;
    float w0, w1;
    if (tap < 27) { w0 = Wc[tap * 4096 + k * 64 + n]; w1 = Wc[tap * 4096 + (k + 1) * 64 + n]; }
    else          { w0 = Wl[k * 64 + n];              w1 = Wl[(k + 1) * 64 + n]; }
    __half2 p = __floats2half2_rn(w0, w1);
    g_wfB[e] = *(uint32_t*)&p;
}

// ---------- main ----------
__global__ __launch_bounds__(NTHREADS, 4)
void conv_mma_kernel(const int* __restrict__ nb, const float* __restrict__ bc,
                     const float* __restrict__ bl, const float* __restrict__ gamma,
                     const float* __restrict__ beta, float* __restrict__ out)
{
    extern __shared__ __align__(16) char smem[];
    const uint32_t sb = smem_u32(smem);
    const int tid   = threadIdx.x;
    const int lane  = tid & 31;
    const int w     = tid >> 5;
    const int qp    = lane & 3;
    const int gvox  = blockIdx.x * NTHREADS + tid;
    const bool active = gvox < N_VOX;
    const int* nrow = nb + (long)gvox * NK;

    // ---- zero both A stages once ----
    {
        uint4 z = make_uint4(0, 0, 0, 0);
        #pragma unroll
        for (int t = 0; t < 18; t++) {
            int o = (tid + t * NTHREADS) * 16;
            if (o < SMEM_BYTES) *(uint4*)(smem + o) = z;
        }
    }
    __syncthreads();

    float c[2][8][4];
    #pragma unroll
    for (int mi = 0; mi < 2; mi++)
        #pragma unroll
        for (int nt = 0; nt < 8; nt++)
            #pragma unroll
            for (int r = 0; r < 4; r++) c[mi][nt][r] = 0.f;

    // per-thread row-valid history for each stage
    bool prevv[2] = {false, false};
    const uint32_t myrow[2] = { sb + tid * ROWB, sb + STAGE_A + tid * ROWB };

    auto maintain = [&](int s, int k) {   // prepare stage s for tap k
        bool cur = active && (nrow[k] >= 0);
        if (cur) {
            const char* src = (const char*)(g_f16 + (size_t)nrow[k] * 64);
            #pragma unroll
            for (int j = 0; j < 8; j++) cpa16(myrow[s] + j * 16, src + j * 16);
        } else if (prevv[s]) {
            uint4 z = make_uint4(0, 0, 0, 0);
            char* dst = smem + s * STAGE_A + tid * ROWB;
            #pragma unroll
            for (int j = 0; j < 8; j++) *(uint4*)(dst + j * 16) = z;
        }
        prevv[s] = cur;
    };

    // ldmatrix base address for this lane (per mi/k4 added later)
    // addr = stage + (w*32 + mi*16 + (lane&15))*ROWB + (lane>>4)*16 + k4*32
    const uint32_t lm_base = sb + (w * 32 + (lane & 15)) * ROWB + (lane >> 4) * 16;

    // ---- prologue: taps 0,1 ----
    maintain(0, 0); CP_COMMIT();
    maintain(1, 1); CP_COMMIT();

    // ---- dense 27-tap mainloop ----
    #pragma unroll 1
    for (int k = 0; k < NK; k++) {
        const int s = k & 1;
        if (k < NK - 1) CP_WAIT(1); else CP_WAIT(0);
        __syncthreads();

        // load all A fragments for this tap (8 x ldmatrix.x4)
        uint32_t a[2][4][4];
        #pragma unroll
        for (int mi = 0; mi < 2; mi++)
            #pragma unroll
            for (int k4 = 0; k4 < 4; k4++)
                ldsm4(a[mi][k4], lm_base + s * STAGE_A + mi * 16 * ROWB + k4 * 32);
        __syncthreads();

        // refill/clean this stage for tap k+2 (overlaps with MMA below)
        if (k + 2 < NK) { maintain(s, k + 2); CP_COMMIT(); }

        // MMA: B fragments streamed from gmem (L1-hot)
        const uint4* wf = (const uint4*)(g_wfB + (((size_t)k * 8) * 32 + lane) * 8);
        #pragma unroll
        for (int nt = 0; nt < 8; nt++) {
            uint4 b01 = wf[nt * 64];        // regs k4=0,1
            uint4 b23 = wf[nt * 64 + 1];    // regs k4=2,3
            mma16816(c[0][nt], a[0][0], b01.x, b01.y);
            mma16816(c[1][nt], a[1][0], b01.x, b01.y);
            mma16816(c[0][nt], a[0][1], b01.z, b01.w);
            mma16816(c[1][nt], a[1][1], b01.z, b01.w);
            mma16816(c[0][nt], a[0][2], b23.x, b23.y);
            mma16816(c[1][nt], a[1][2], b23.x, b23.y);
            mma16816(c[0][nt], a[0][3], b23.z, b23.w);
            mma16816(c[1][nt], a[1][3], b23.z, b23.w);
        }
    }

    // ---- epilogue: +bc, fp16 X into stage0 ----
    const int group = lane >> 2;
    #pragma unroll
    for (int nt = 0; nt < 8; nt++) {
        const int col = nt * 8 + qp * 2;
        const float b0 = bc[col], b1 = bc[col + 1];
        #pragma unroll
        for (int mi = 0; mi < 2; mi++) {
            const int r0 = w * 32 + mi * 16 + group;
            float x0 = c[mi][nt][0] + b0;
            float x1 = c[mi][nt][1] + b1;
            float x2 = c[mi][nt][2] + b0;
            float x3 = c[mi][nt][3] + b1;
            __half2 p0 = __floats2half2_rn(x0, x1);
            __half2 p1 = __floats2half2_rn(x2, x3);
            *(uint32_t*)(smem + r0 * ROWB + col * 2)       = *(uint32_t*)&p0;
            *(uint32_t*)(smem + (r0 + 8) * ROWB + col * 2) = *(uint32_t*)&p1;
        }
    }
    __syncthreads();

    // ---- linear GEMM (tap 27) ----
    #pragma unroll
    for (int mi = 0; mi < 2; mi++)
        #pragma unroll
        for (int nt = 0; nt < 8; nt++)
            #pragma unroll
            for (int r = 0; r < 4; r++) c[mi][nt][r] = 0.f;
    {
        uint32_t a[2][4][4];
        #pragma unroll
        for (int mi = 0; mi < 2; mi++)
            #pragma unroll
            for (int k4 = 0; k4 < 4; k4++)
                ldsm4(a[mi][k4], lm_base + mi * 16 * ROWB + k4 * 32);
        const uint4* wf = (const uint4*)(g_wfB + (((size_t)27 * 8) * 32 + lane) * 8);
        #pragma unroll
        for (int nt = 0; nt < 8; nt++) {
            uint4 b01 = wf[nt * 64];
            uint4 b23 = wf[nt * 64 + 1];
            mma16816(c[0][nt], a[0][0], b01.x, b01.y);
            mma16816(c[1][nt], a[1][0], b01.x, b01.y);
            mma16816(c[0][nt], a[0][1], b01.z, b01.w);
            mma16816(c[1][nt], a[1][1], b01.z, b01.w);
            mma16816(c[0][nt], a[0][2], b23.x, b23.y);
            mma16816(c[1][nt], a[1][2], b23.x, b23.y);
            mma16816(c[0][nt], a[0][3], b23.z, b23.w);
            mma16816(c[1][nt], a[1][3], b23.z, b23.w);
        }
    }

    // ---- +bl, layernorm, store ----
    float sum[2][2] = {{0.f, 0.f}, {0.f, 0.f}};
    float sq [2][2] = {{0.f, 0.f}, {0.f, 0.f}};
    #pragma unroll
    for (int nt = 0; nt < 8; nt++) {
        const int col = nt * 8 + qp * 2;
        const float b0 = bl[col], b1 = bl[col + 1];
        #pragma unroll
        for (int mi = 0; mi < 2; mi++) {
            float y0 = c[mi][nt][0] + b0, y1 = c[mi][nt][1] + b1;
            float y2 = c[mi][nt][2] + b0, y3 = c[mi][nt][3] + b1;
            c[mi][nt][0] = y0; c[mi][nt][1] = y1;
            c[mi][nt][2] = y2; c[mi][nt][3] = y3;
            sum[mi][0] += y0 + y1;  sq[mi][0] += y0 * y0 + y1 * y1;
            sum[mi][1] += y2 + y3;  sq[mi][1] += y2 * y2 + y3 * y3;
        }
    }
    #pragma unroll
    for (int off = 1; off <= 2; off <<= 1) {
        #pragma unroll
        for (int mi = 0; mi < 2; mi++)
            #pragma unroll
            for (int h = 0; h < 2; h++) {
                sum[mi][h] += __shfl_xor_sync(0xffffffffu, sum[mi][h], off);
                sq [mi][h] += __shfl_xor_sync(0xffffffffu, sq [mi][h], off);
            }
    }
    float mu[2][2], rs[2][2];
    #pragma unroll
    for (int mi = 0; mi < 2; mi++)
        #pragma unroll
        for (int h = 0; h < 2; h++) {
            float m = sum[mi][h] * (1.0f / 64.0f);
            float v = sq[mi][h] * (1.0f / 64.0f) - m * m;
            mu[mi][h] = m;
            rs[mi][h] = rsqrtf(v + LN_EPS);
        }
    const int base_row = blockIdx.x * NTHREADS + w * 32 + group;
    #pragma unroll
    for (int nt = 0; nt < 8; nt++) {
        const int col = nt * 8 + qp * 2;
        const float g0 = gamma[col], g1 = gamma[col + 1];
        const float be0 = beta[col], be1 = beta[col + 1];
        #pragma unroll
        for (int mi = 0; mi < 2; mi++) {
            int r0 = base_row + mi * 16;
            int r1 = r0 + 8;
            if (r0 < N_VOX) {
                float2 o;
                o.x = g0 * (c[mi][nt][0] - mu[mi][0]) * rs[mi][0] + be0;
                o.y = g1 * (c[mi][nt][1] - mu[mi][0]) * rs[mi][0] + be1;
                *(float2*)(out + (size_t)r0 * 64 + col) = o;
            }
            if (r1 < N_VOX) {
                float2 o;
                o.x = g0 * (c[mi][nt][2] - mu[mi][1]) * rs[mi][1] + be0;
                o.y = g1 * (c[mi][nt][3] - mu[mi][1]) * rs[mi][1] + be1;
                *(float2*)(out + (size_t)r1 * 64 + col) = o;
            }
        }
    }
}

// ---------- launch ----------
extern "C" void kernel_launch(void* const* d_in, const int* in_sizes, int n_in,
                              void* d_out, int out_size)
{
    const float* feats = (const float*)d_in[0];
    const int*   nb    = (const int*)d_in[1];
    const float* Wc    = (const float*)d_in[2];
    const float* bc    = (const float*)d_in[3];
    const float* Wl    = (const float*)d_in[4];
    const float* bl    = (const float*)d_in[5];
    const float* gamma = (const float*)d_in[6];
    const float* beta  = (const float*)d_in[7];
    float* out = (float*)d_out;

    static int init = 0;
    if (!init) {
        cudaFuncSetAttribute(conv_mma_kernel,
                             cudaFuncAttributeMaxDynamicSharedMemorySize, SMEM_BYTES);
        init = 1;
    }
    prep_feats<<<(N_VOX * 8 + 255) / 256, 256>>>(feats);
    prep_wfB<<<(28 * 2048 + 255) / 256, 256>>>(Wc, Wl);
    conv_mma_kernel<<<GRID_M, NTHREADS, SMEM_BYTES>>>(nb, bc, bl, gamma, beta, out);
}

// round 12
// speedup vs baseline: 1.0981x; 1.0553x over previous
#include <cuda_runtime.h>
#include <cuda_fp16.h>
#include <cstdint>

#define N_VOX    100000
#define NK       27
#define LN_EPS   1e-5f
#define NTHREADS 128
#define GRID_M   ((N_VOX + 127) / 128)   // 782

// smem stage: A 128x(64+8 pad) fp16 = 18432B ; W 64x(64+8) fp16 = 9216B
#define ROWB    144                      // row stride bytes (72 fp16)
#define A_BYTES 18432
#define STAGE   27648
#define SMEM_BYTES (2 * STAGE)           // 55296

// Precomputed data (static device globals, no allocation)
__device__ __align__(16) __half g_f16[N_VOX * 64];
__device__ __align__(16) __half g_w16[28 * 4096];   // [tap][cout][cin], tap27 = W_lin
__device__ int g_nbT[NK * N_VOX];                   // transposed neighbor table [k][vox]

// ---------- helpers ----------
__device__ __forceinline__ uint32_t smem_u32(const void* p) {
    uint32_t a;
    asm("{ .reg .u64 t; cvta.to.shared.u64 t, %1; cvt.u32.u64 %0, t; }" : "=r"(a) : "l"(p));
    return a;
}
__device__ __forceinline__ uint32_t lds32(uint32_t a) {
    uint32_t v;
    asm volatile("ld.shared.b32 %0, [%1];" : "=r"(v) : "r"(a));
    return v;
}
__device__ __forceinline__ void sts32(uint32_t a, uint32_t v) {
    asm volatile("st.shared.b32 [%0], %1;" :: "r"(a), "r"(v));
}
__device__ __forceinline__ void cpa16(uint32_t dst, const void* src) {
    asm volatile("cp.async.cg.shared.global [%0], [%1], 16;" :: "r"(dst), "l"(src));
}
__device__ __forceinline__ void cpa16_ca(uint32_t dst, const void* src) {
    asm volatile("cp.async.ca.shared.global [%0], [%1], 16;" :: "r"(dst), "l"(src));
}
#define CP_COMMIT()  asm volatile("cp.async.commit_group;" ::: "memory")
#define CP_WAIT(n)   asm volatile("cp.async.wait_group %0;" :: "n"(n) : "memory")

__device__ __forceinline__ void mma16816(float* c, const uint32_t* a,
                                         uint32_t b0, uint32_t b1) {
    asm volatile(
        "mma.sync.aligned.m16n8k16.row.col.f32.f16.f16.f32 "
        "{%0,%1,%2,%3}, {%4,%5,%6,%7}, {%8,%9}, {%0,%1,%2,%3};"
        : "+f"(c[0]), "+f"(c[1]), "+f"(c[2]), "+f"(c[3])
        : "r"(a[0]), "r"(a[1]), "r"(a[2]), "r"(a[3]), "r"(b0), "r"(b1));
}

// ---------- pre-kernels ----------
#define FEAT_BLOCKS 3125                 // N_VOX*8 / 256
#define NBT_BLOCKS  391                  // ceil(100000/256)

__global__ void prep_all(const float* __restrict__ feats, const int* __restrict__ nb) {
    __shared__ int tile[256 * NK];
    int b = blockIdx.x;
    if (b < FEAT_BLOCKS) {
        int t = b * blockDim.x + threadIdx.x;      // 8 floats / thread
        if (t >= N_VOX * 8) return;
        const float4* F = (const float4*)feats;
        float4 f0 = F[t * 2], f1 = F[t * 2 + 1];
        __half2 h0 = __floats2half2_rn(f0.x, f0.y);
        __half2 h1 = __floats2half2_rn(f0.z, f0.w);
        __half2 h2 = __floats2half2_rn(f1.x, f1.y);
        __half2 h3 = __floats2half2_rn(f1.z, f1.w);
        uint4 o;
        o.x = *(uint32_t*)&h0; o.y = *(uint32_t*)&h1;
        o.z = *(uint32_t*)&h2; o.w = *(uint32_t*)&h3;
        ((uint4*)g_f16)[t] = o;
    } else {
        // nb transpose: 256 voxels per block
        int base = (b - FEAT_BLOCKS) * 256;
        for (int i = threadIdx.x; i < 256 * NK; i += blockDim.x) {
            long src = (long)base * NK + i;
            tile[i] = (src < (long)N_VOX * NK) ? nb[src] : -1;
        }
        __syncthreads();
        int v = base + threadIdx.x;
        if (v < N_VOX) {
            #pragma unroll
            for (int k = 0; k < NK; k++)
                g_nbT[k * N_VOX + v] = tile[threadIdx.x * NK + k];
        }
    }
}
__global__ void prep_w(const float* __restrict__ Wc, const float* __restrict__ Wl) {
    int e = blockIdx.x * blockDim.x + threadIdx.x;       // (tap, o, c)
    if (e >= 28 * 4096) return;
    int k = e >> 12, rem = e & 4095;
    int o = rem >> 6, c = rem & 63;
    float w = (k < 27) ? Wc[k * 4096 + c * 64 + o] : Wl[c * 64 + o];
    g_w16[e] = __float2half_rn(w);
}

// ---------- main ----------
__global__ __launch_bounds__(NTHREADS, 4)
void conv_mma_kernel(const float* __restrict__ bc,
                     const float* __restrict__ bl, const float* __restrict__ gamma,
                     const float* __restrict__ beta, float* __restrict__ out)
{
    extern __shared__ __align__(16) char smem[];
    const uint32_t sb = smem_u32(smem);
    const int tid  = threadIdx.x;
    const int lane = tid & 31;
    const int w    = tid >> 5;
    const int group = lane >> 2;     // 0..7
    const int qp    = lane & 3;      // 0..3
    const int gvox = blockIdx.x * NTHREADS + tid;
    const bool active = gvox < N_VOX;

    float c[2][8][4];
    #pragma unroll
    for (int mi = 0; mi < 2; mi++)
        #pragma unroll
        for (int nt = 0; nt < 8; nt++)
            #pragma unroll
            for (int r = 0; r < 4; r++) c[mi][nt][r] = 0.0f;

    // ---- issue helpers ----
    auto issueA = [&](int s, int k) {
        uint32_t dst = sb + s * STAGE + tid * ROWB;
        int idx = active ? g_nbT[k * N_VOX + gvox] : -1;   // coalesced
        if (idx >= 0) {
            const char* src = (const char*)(g_f16 + (size_t)idx * 64);
            #pragma unroll
            for (int j = 0; j < 8; j++) cpa16(dst + j * 16, src + j * 16);
        } else {
            float4 z = make_float4(0.f, 0.f, 0.f, 0.f);
            #pragma unroll
            for (int j = 0; j < 8; j++)
                *(float4*)(smem + s * STAGE + tid * ROWB + j * 16) = z;
        }
    };
    auto issueW = [&](uint32_t wbase, int k) {
        const char* srcb = (const char*)(g_w16 + (size_t)k * 4096);
        #pragma unroll
        for (int t = 0; t < 4; t++) {
            int ch = tid + t * 128;          // 512 chunks of 16B
            int row = ch >> 3, j = ch & 7;
            cpa16_ca(wbase + row * ROWB + j * 16, srcb + ch * 16);   // L1-cached
        }
    };
    auto do_tap = [&](uint32_t Ab, uint32_t Wb) {
        #pragma unroll
        for (int k4 = 0; k4 < 4; k4++) {
            const int k0 = k4 * 16;
            uint32_t a[2][4];
            #pragma unroll
            for (int mi = 0; mi < 2; mi++) {
                uint32_t base = Ab + (w * 32 + mi * 16 + group) * ROWB + (k0 + qp * 2) * 2;
                a[mi][0] = lds32(base);
                a[mi][1] = lds32(base + 8 * ROWB);
                a[mi][2] = lds32(base + 16);
                a[mi][3] = lds32(base + 8 * ROWB + 16);
            }
            #pragma unroll
            for (int nt = 0; nt < 8; nt++) {
                uint32_t baddr = Wb + (nt * 8 + group) * ROWB + (k0 + qp * 2) * 2;
                uint32_t b0 = lds32(baddr);
                uint32_t b1 = lds32(baddr + 16);
                mma16816(c[0][nt], a[0], b0, b1);
                mma16816(c[1][nt], a[1], b0, b1);
            }
        }
    };

    // ---- prologue: taps 0,1 ----
    issueA(0, 0); issueW(sb + 0 * STAGE + A_BYTES, 0); CP_COMMIT();
    issueA(1, 1); issueW(sb + 1 * STAGE + A_BYTES, 1); CP_COMMIT();

    // ---- conv mainloop ----
    #pragma unroll 1
    for (int k = 0; k < NK; k++) {
        const int s = k & 1;
        if (k < NK - 1) CP_WAIT(1); else CP_WAIT(0);
        __syncthreads();
        do_tap(sb + s * STAGE, sb + s * STAGE + A_BYTES);
        __syncthreads();
        if (k + 2 < NK) {
            issueA(s, k + 2);
            issueW(sb + s * STAGE + A_BYTES, k + 2);
            CP_COMMIT();
        }
    }

    // ---- epilogue: +bc, convert to fp16 X in stage0 A; load W_lin ----
    issueW(sb + A_BYTES, 27); CP_COMMIT();
    #pragma unroll
    for (int nt = 0; nt < 8; nt++) {
        const int col0 = nt * 8 + qp * 2;
        const float b0 = bc[col0], b1 = bc[col0 + 1];
        #pragma unroll
        for (int mi = 0; mi < 2; mi++) {
            float x0 = c[mi][nt][0] + b0;
            float x1 = c[mi][nt][1] + b1;
            float x2 = c[mi][nt][2] + b0;
            float x3 = c[mi][nt][3] + b1;
            __half2 p0 = __floats2half2_rn(x0, x1);
            __half2 p1 = __floats2half2_rn(x2, x3);
            const int r0 = w * 32 + mi * 16 + group;
            sts32(sb + r0 * ROWB + col0 * 2, *(uint32_t*)&p0);
            sts32(sb + (r0 + 8) * ROWB + col0 * 2, *(uint32_t*)&p1);
        }
    }
    CP_WAIT(0);
    __syncthreads();

    // ---- linear GEMM (tap 27) ----
    #pragma unroll
    for (int mi = 0; mi < 2; mi++)
        #pragma unroll
        for (int nt = 0; nt < 8; nt++)
            #pragma unroll
            for (int r = 0; r < 4; r++) c[mi][nt][r] = 0.0f;
    do_tap(sb, sb + A_BYTES);

    // ---- +bl, layernorm in registers ----
    float sum[2][2] = {{0.f, 0.f}, {0.f, 0.f}};
    float sq [2][2] = {{0.f, 0.f}, {0.f, 0.f}};
    #pragma unroll
    for (int nt = 0; nt < 8; nt++) {
        const int col0 = nt * 8 + qp * 2;
        const float b0 = bl[col0], b1 = bl[col0 + 1];
        #pragma unroll
        for (int mi = 0; mi < 2; mi++) {
            float y0 = c[mi][nt][0] + b0, y1 = c[mi][nt][1] + b1;
            float y2 = c[mi][nt][2] + b0, y3 = c[mi][nt][3] + b1;
            c[mi][nt][0] = y0; c[mi][nt][1] = y1;
            c[mi][nt][2] = y2; c[mi][nt][3] = y3;
            sum[mi][0] += y0 + y1;            sq[mi][0] += y0 * y0 + y1 * y1;
            sum[mi][1] += y2 + y3;            sq[mi][1] += y2 * y2 + y3 * y3;
        }
    }
    #pragma unroll
    for (int off = 1; off <= 2; off <<= 1) {
        #pragma unroll
        for (int mi = 0; mi < 2; mi++)
            #pragma unroll
            for (int h = 0; h < 2; h++) {
                sum[mi][h] += __shfl_xor_sync(0xffffffffu, sum[mi][h], off);
                sq [mi][h] += __shfl_xor_sync(0xffffffffu, sq [mi][h], off);
            }
    }
    float mu[2][2], rs[2][2];
    #pragma unroll
    for (int mi = 0; mi < 2; mi++)
        #pragma unroll
        for (int h = 0; h < 2; h++) {
            float m = sum[mi][h] * (1.0f / 64.0f);
            float v = sq[mi][h] * (1.0f / 64.0f) - m * m;
            mu[mi][h] = m;
            rs[mi][h] = rsqrtf(v + LN_EPS);
        }
    const int base_row = blockIdx.x * NTHREADS + w * 32 + group;
    #pragma unroll
    for (int nt = 0; nt < 8; nt++) {
        const int col0 = nt * 8 + qp * 2;
        const float g0 = gamma[col0], g1 = gamma[col0 + 1];
        const float be0 = beta[col0], be1 = beta[col0 + 1];
        #pragma unroll
        for (int mi = 0; mi < 2; mi++) {
            int r0 = base_row + mi * 16;
            int r1 = r0 + 8;
            if (r0 < N_VOX) {
                float2 o;
                o.x = g0 * (c[mi][nt][0] - mu[mi][0]) * rs[mi][0] + be0;
                o.y = g1 * (c[mi][nt][1] - mu[mi][0]) * rs[mi][0] + be1;
                *(float2*)(out + (size_t)r0 * 64 + col0) = o;
            }
            if (r1 < N_VOX) {
                float2 o;
                o.x = g0 * (c[mi][nt][2] - mu[mi][1]) * rs[mi][1] + be0;
                o.y = g1 * (c[mi][nt][3] - mu[mi][1]) * rs[mi][1] + be1;
                *(float2*)(out + (size_t)r1 * 64 + col0) = o;
            }
        }
    }
}

// ---------- launch ----------
extern "C" void kernel_launch(void* const* d_in, const int* in_sizes, int n_in,
                              void* d_out, int out_size)
{
    const float* feats = (const float*)d_in[0];
    const int*   nb    = (const int*)d_in[1];
    const float* Wc    = (const float*)d_in[2];
    const float* bc    = (const float*)d_in[3];
    const float* Wl    = (const float*)d_in[4];
    const float* bl    = (const float*)d_in[5];
    const float* gamma = (const float*)d_in[6];
    const float* beta  = (const float*)d_in[7];
    float* out = (float*)d_out;

    static int init = 0;
    if (!init) {
        cudaFuncSetAttribute(conv_mma_kernel,
                             cudaFuncAttributeMaxDynamicSharedMemorySize, SMEM_BYTES);
        init = 1;
    }
    prep_all<<<FEAT_BLOCKS + NBT_BLOCKS, 256>>>(feats, nb);
    prep_w<<<(28 * 4096 + 255) / 256, 256>>>(Wc, Wl);
    conv_mma_kernel<<<GRID_M, NTHREADS, SMEM_BYTES>>>(bc, bl, gamma, beta, out);
}